// round 2
// baseline (speedup 1.0000x reference)
#include <cuda_runtime.h>
#include <math.h>

#define B_DIM 256
#define N_DIM 256
#define D_DIM 512
#define MARGIN 0.5f
#define EPS_V 1e-6f
#define ROWS (B_DIM * N_DIM)           // 65536
#define BND ((size_t)ROWS * D_DIM)     // 33554432

// ---- scratch (device globals; no allocation allowed) ----
__device__ float g_dp[ROWS];
__device__ float g_dn[ROWS];
__device__ float g_loss_partial[B_DIM];
__device__ int   g_neg_idx[B_DIM];
__device__ int   g_pos_idx[B_DIM];
__device__ int   g_valid_neg[B_DIM];
__device__ int   g_valid_pos[B_DIM];

// ============================================================
// Kernel 1: per-row L2 distances. WARP-per-row.
// Each thread loads 4 float4 from each of the 3 tensors (12 independent
// LDG.128 in flight), then warp-shuffle reduction. No smem, no bar.sync.
// Block = 256 threads = 8 rows; grid = ROWS/8.
// ============================================================
__global__ __launch_bounds__(256) void dist_kernel(
    const float* __restrict__ anchor,
    const float* __restrict__ positive,
    const float* __restrict__ negative)
{
    const int row  = blockIdx.x * 8 + (threadIdx.x >> 5);
    const int lane = threadIdx.x & 31;

    const float4* a4 = (const float4*)(anchor   + (size_t)row * D_DIM);
    const float4* p4 = (const float4*)(positive + (size_t)row * D_DIM);
    const float4* n4 = (const float4*)(negative + (size_t)row * D_DIM);

    float4 av[4], pv[4], nv[4];
    #pragma unroll
    for (int i = 0; i < 4; i++) av[i] = a4[lane + 32 * i];
    #pragma unroll
    for (int i = 0; i < 4; i++) pv[i] = p4[lane + 32 * i];
    #pragma unroll
    for (int i = 0; i < 4; i++) nv[i] = n4[lane + 32 * i];

    float dp = 0.0f, dn = 0.0f;
    #pragma unroll
    for (int i = 0; i < 4; i++) {
        float x0 = av[i].x - pv[i].x + EPS_V, x1 = av[i].y - pv[i].y + EPS_V;
        float x2 = av[i].z - pv[i].z + EPS_V, x3 = av[i].w - pv[i].w + EPS_V;
        dp += x0*x0 + x1*x1 + x2*x2 + x3*x3;
        float y0 = av[i].x - nv[i].x + EPS_V, y1 = av[i].y - nv[i].y + EPS_V;
        float y2 = av[i].z - nv[i].z + EPS_V, y3 = av[i].w - nv[i].w + EPS_V;
        dn += y0*y0 + y1*y1 + y2*y2 + y3*y3;
    }

    #pragma unroll
    for (int off = 16; off > 0; off >>= 1) {
        dp += __shfl_xor_sync(0xFFFFFFFFu, dp, off);
        dn += __shfl_xor_sync(0xFFFFFFFFu, dn, off);
    }

    if (lane == 0) {
        g_dp[row] = sqrtf(dp);
        g_dn[row] = sqrtf(dn);
    }
}

// ============================================================
// Kernel 2: per-batch hard mining + loss partials.
// One block (256 thr) per batch b, thread n handles element n.
// argmax/argmin with first-occurrence (lowest index) tie-break.
// ============================================================
__global__ __launch_bounds__(256) void mine_kernel(float* __restrict__ out)
{
    const int b = blockIdx.x;
    const int n = threadIdx.x;

    const float dp = g_dp[b * N_DIM + n];
    const float dn = g_dn[b * N_DIM + n];

    const bool mask_neg = (dp - dn + MARGIN) > 0.0f;
    const bool mask_pos = (dn - dp + MARGIN) > 0.0f;

    __shared__ float s_sn[N_DIM]; __shared__ int s_in[N_DIM];
    __shared__ float s_sp[N_DIM]; __shared__ int s_ip[N_DIM];
    __shared__ float s_l [N_DIM];

    s_sn[n] = mask_neg ? dn : -INFINITY;  s_in[n] = n;
    s_sp[n] = mask_pos ? dp :  INFINITY;  s_ip[n] = n;
    s_l [n] = fmaxf(0.0f, MARGIN + dp - dn);
    __syncthreads();

    for (int off = N_DIM / 2; off > 0; off >>= 1) {
        if (n < off) {
            float so = s_sn[n + off]; int io = s_in[n + off];
            if (so > s_sn[n] || (so == s_sn[n] && io < s_in[n])) {
                s_sn[n] = so; s_in[n] = io;
            }
            float qo = s_sp[n + off]; int jo = s_ip[n + off];
            if (qo < s_sp[n] || (qo == s_sp[n] && jo < s_ip[n])) {
                s_sp[n] = qo; s_ip[n] = jo;
            }
            s_l[n] += s_l[n + off];
        }
        __syncthreads();
    }

    if (n == 0) {
        const int vn = (s_sn[0] > -INFINITY) ? 1 : 0;
        const int vp = (s_sp[0] <  INFINITY) ? 1 : 0;
        g_neg_idx[b] = s_in[0];
        g_pos_idx[b] = s_ip[0];
        g_valid_neg[b] = vn;
        g_valid_pos[b] = vp;
        g_loss_partial[b] = s_l[0];
        out[1 + 2 * BND + b]         = (float)vn;
        out[1 + 2 * BND + B_DIM + b] = (float)vp;
    }
}

// ============================================================
// Kernel 3: deterministic loss finalize (single block).
// ============================================================
__global__ __launch_bounds__(256) void loss_kernel(float* __restrict__ out)
{
    const int t = threadIdx.x;
    __shared__ float s[B_DIM];
    s[t] = g_loss_partial[t];
    __syncthreads();
    for (int off = B_DIM / 2; off > 0; off >>= 1) {
        if (t < off) s[t] += s[t + off];
        __syncthreads();
    }
    if (t == 0) out[0] = s[0] * (1.0f / (float)(B_DIM * N_DIM));
}

// ============================================================
// Kernel 4: gather + write hard_neg / hard_pos.
// One block (128 thr) per (b,n) row.
// Output base is out+1 (4B-misaligned vs 16B), so the row is written as
// 3 head scalars + 127 aligned STG.128 + 1 tail scalar.
// Byte addr of out+1+row*512+3 = out + (4+512*row)*4  ->  0 mod 16.
// Loads are scalar (warp-contiguous; L1 coalesces to the same sectors).
// ============================================================
__global__ __launch_bounds__(128) void gather_kernel(
    const float* __restrict__ positive,
    const float* __restrict__ negative,
    float* __restrict__ out)
{
    const int row = blockIdx.x;
    const int b = row >> 8;       // N_DIM == 256
    const int n = row & (N_DIM - 1);
    const int t = threadIdx.x;

    const int  ni = g_neg_idx[b];
    const int  pi = g_pos_idx[b];
    const bool vn = g_valid_neg[b] != 0;
    const bool vp = g_valid_pos[b] != 0;

    // N-index used as BATCH index (faithful to reference)
    const float* nsrc = negative + ((size_t)ni * N_DIM + n) * D_DIM;
    const float* psrc = positive + ((size_t)pi * N_DIM + n) * D_DIM;

    float* hn = out + 1 +       (size_t)row * D_DIM;
    float* hp = out + 1 + BND + (size_t)row * D_DIM;

    if (t < 127) {
        const int e = 3 + 4 * t;
        float4 v, w;
        if (vn) {
            v.x = __ldg(&nsrc[e+0]); v.y = __ldg(&nsrc[e+1]);
            v.z = __ldg(&nsrc[e+2]); v.w = __ldg(&nsrc[e+3]);
        } else v = make_float4(0.f, 0.f, 0.f, 0.f);
        if (vp) {
            w.x = __ldg(&psrc[e+0]); w.y = __ldg(&psrc[e+1]);
            w.z = __ldg(&psrc[e+2]); w.w = __ldg(&psrc[e+3]);
        } else w = make_float4(0.f, 0.f, 0.f, 0.f);
        *(float4*)(hn + e) = v;
        *(float4*)(hp + e) = w;
    } else {
        // t == 127: head scalars 0,1,2 and tail scalar 511
        hn[0]   = vn ? __ldg(&nsrc[0])   : 0.0f;
        hn[1]   = vn ? __ldg(&nsrc[1])   : 0.0f;
        hn[2]   = vn ? __ldg(&nsrc[2])   : 0.0f;
        hn[511] = vn ? __ldg(&nsrc[511]) : 0.0f;
        hp[0]   = vp ? __ldg(&psrc[0])   : 0.0f;
        hp[1]   = vp ? __ldg(&psrc[1])   : 0.0f;
        hp[2]   = vp ? __ldg(&psrc[2])   : 0.0f;
        hp[511] = vp ? __ldg(&psrc[511]) : 0.0f;
    }
}

// ============================================================
extern "C" void kernel_launch(void* const* d_in, const int* in_sizes, int n_in,
                              void* d_out, int out_size)
{
    const float* anchor   = (const float*)d_in[0];
    const float* positive = (const float*)d_in[1];
    const float* negative = (const float*)d_in[2];
    float* out = (float*)d_out;

    dist_kernel  <<<ROWS / 8, 256>>>(anchor, positive, negative);
    mine_kernel  <<<B_DIM, 256>>>(out);
    loss_kernel  <<<1, 256>>>(out);
    gather_kernel<<<ROWS, 128>>>(positive, negative, out);
}